// round 16
// baseline (speedup 1.0000x reference)
#include <cuda_runtime.h>
#include <cuda_bf16.h>

#define NUM_CLASSES 1000
#define VEC_PER_ROW 250          // 1000 floats / 4
#define ROWS_PER_BLOCK 8         // 8 warps per 256-thread block, 1 warp per row
#define MAX_BLOCKS 16384

// Static device scratch (no allocation).
__device__ double       g_partials[MAX_BLOCKS];
__device__ unsigned int g_count = 0;   // reset to 0 by the last block each call

__global__ __launch_bounds__(256, 8) void hloss_fused(
    const float* __restrict__ outputs,
    const int*   __restrict__ target,
    float*       __restrict__ out,
    int B)
{
    const int warp = threadIdx.x >> 5;
    const int lane = threadIdx.x & 31;
    const int row  = blockIdx.x * ROWS_PER_BLOCK + warp;

    float one_minus_win = 0.0f;

    if (row < B) {
        const float* rowp = outputs + (size_t)row * NUM_CLASSES;
        const float4* r4  = reinterpret_cast<const float4*>(rowp);

        // ---- main streaming sum: 250 float4 per row, lane-strided, MLP=8 ----
        float s0 = 0.f, s1 = 0.f, s2 = 0.f, s3 = 0.f;
        #pragma unroll
        for (int i = 0; i < 7; i++) {
            float4 x = r4[lane + 32 * i];
            s0 += x.x; s1 += x.y; s2 += x.z; s3 += x.w;
        }
        if (lane < VEC_PER_ROW - 7 * 32) {   // lanes 0..25 handle the tail
            float4 x = r4[lane + 224];
            s0 += x.x; s1 += x.y; s2 += x.z; s3 += x.w;
        }
        float sall = (s0 + s1) + (s2 + s3);

        // ---- hierarchy-local terms (L1-hot re-reads) ----
        const int t = target[row];
        const int g = t / 100;   // 100-leaf block id
        const int h = t / 10;    // 10-leaf block id

        // 100-block: 25 aligned float4s, weight 0.25
        float s100 = 0.f;
        if (lane < 25) {
            float4 x = r4[g * 25 + lane];
            s100 = (x.x + x.y) + (x.z + x.w);
        }

        // 10-block (weight 0.125) + extra target term (another 0.125 on c==t)
        float s10t = 0.f;
        if (lane < 10) {
            int c = h * 10 + lane;
            float x = rowp[c];
            s10t = x * ((c == t) ? 0.25f : 0.125f);
        }

        // per-lane contribution to win (weights distribute over the lane sum)
        float v = 0.5f * sall + 0.25f * s100 + s10t;

        // warp reduction -> win for this row
        #pragma unroll
        for (int o = 16; o > 0; o >>= 1)
            v += __shfl_xor_sync(0xffffffffu, v, o);

        if (lane == 0) one_minus_win = 1.0f - v;
    }

    // ---- block reduction of the 8 per-row (1 - win) values ----
    __shared__ float sh[ROWS_PER_BLOCK];
    __shared__ bool  is_last;
    if (lane == 0) sh[warp] = one_minus_win;
    __syncthreads();
    if (threadIdx.x == 0) {
        float bs = 0.f;
        #pragma unroll
        for (int w = 0; w < ROWS_PER_BLOCK; w++) bs += sh[w];
        g_partials[blockIdx.x] = (double)bs;
        __threadfence();
        unsigned int prev = atomicAdd(&g_count, 1u);
        is_last = (prev == gridDim.x - 1);
        if (is_last) g_count = 0;           // reset for the next graph replay
    }
    __syncthreads();

    // ---- last arriving block performs the deterministic final sum ----
    if (is_last) {
        double s = 0.0;
        for (int i = threadIdx.x; i < (int)gridDim.x; i += blockDim.x)
            s += g_partials[i];

        // warp reduce (double), fixed tree order -> deterministic
        #pragma unroll
        for (int o = 16; o > 0; o >>= 1)
            s += __shfl_down_sync(0xffffffffu, s, o);

        __shared__ double shd[8];
        if (lane == 0) shd[warp] = s;
        __syncthreads();
        if (threadIdx.x == 0) {
            double tot = 0.0;
            #pragma unroll
            for (int w = 0; w < 8; w++) tot += shd[w];
            out[0] = (float)tot;
        }
    }
}

extern "C" void kernel_launch(void* const* d_in, const int* in_sizes, int n_in,
                              void* d_out, int out_size)
{
    const float* outputs = (const float*)d_in[0];   // [B, 1000] fp32
    const int*   target  = (const int*)d_in[1];     // [B] int32
    const int B = in_sizes[1];

    int nblocks = (B + ROWS_PER_BLOCK - 1) / ROWS_PER_BLOCK;
    if (nblocks > MAX_BLOCKS) nblocks = MAX_BLOCKS;  // bench B=32768 -> 4096 blocks

    hloss_fused<<<nblocks, 256>>>(outputs, target, (float*)d_out, B);
}

// round 17
// speedup vs baseline: 1.2252x; 1.2252x over previous
#include <cuda_runtime.h>
#include <cuda_bf16.h>

#define NUM_CLASSES 1000
#define WARPS_PER_BLOCK 8
#define THREADS 256
#define MAX_BLOCKS 4096

// Static device scratch (no allocation).
__device__ double g_partials[MAX_BLOCKS];

__global__ __launch_bounds__(THREADS, 4) void hloss_main(
    const float* __restrict__ outputs,
    const int*   __restrict__ target,
    int B, int rpw)
{
    const int warp = threadIdx.x >> 5;
    const int lane = threadIdx.x & 31;
    const int gw   = blockIdx.x * WARPS_PER_BLOCK + warp;

    const int r0 = gw * rpw;
    int r1 = r0 + rpw; if (r1 > B) r1 = B;

    float vacc = 0.0f;        // per-lane accumulated win contributions
    int   cnt  = (r1 > r0) ? (r1 - r0) : 0;

    if (r1 > r0) {
        int tnext = target[r0];               // prefetch first target

        for (int r = r0; r < r1; ++r) {
            const int t = tnext;
            if (r + 1 < r1) tnext = target[r + 1];   // prefetch next row's target

            const float* rowp = outputs + (size_t)r * NUM_CLASSES;
            const float4* r4  = reinterpret_cast<const float4*>(rowp);

            // ---- streaming sum: 250 float4, lane-strided, front-batched MLP=8 ----
            float s0 = 0.f, s1 = 0.f, s2 = 0.f, s3 = 0.f;
            float4 x0 = r4[lane +   0];
            float4 x1 = r4[lane +  32];
            float4 x2 = r4[lane +  64];
            float4 x3 = r4[lane +  96];
            float4 x4 = r4[lane + 128];
            float4 x5 = r4[lane + 160];
            float4 x6 = r4[lane + 192];
            float4 x7 = (lane < 26) ? r4[lane + 224]
                                    : make_float4(0.f, 0.f, 0.f, 0.f);
            s0 = (x0.x + x1.x) + (x2.x + x3.x) + (x4.x + x5.x) + (x6.x + x7.x);
            s1 = (x0.y + x1.y) + (x2.y + x3.y) + (x4.y + x5.y) + (x6.y + x7.y);
            s2 = (x0.z + x1.z) + (x2.z + x3.z) + (x4.z + x5.z) + (x6.z + x7.z);
            s3 = (x0.w + x1.w) + (x2.w + x3.w) + (x4.w + x5.w) + (x6.w + x7.w);
            float sall = (s0 + s1) + (s2 + s3);

            // ---- hierarchy-local terms (L1-hot re-reads; t already resident) ----
            const int g = t / 100;   // 100-leaf block id
            const int h = t / 10;    // 10-leaf block id

            float s100 = 0.f;
            if (lane < 25) {
                float4 x = r4[g * 25 + lane];
                s100 = (x.x + x.y) + (x.z + x.w);
            }

            float s10t = 0.f;
            if (lane < 10) {
                int c = h * 10 + lane;
                float x = rowp[c];
                s10t = x * ((c == t) ? 0.25f : 0.125f);
            }

            // per-lane contribution to win (no per-row reduction!)
            vacc += 0.5f * sall + 0.25f * s100 + s10t;
        }
    }

    // ---- ONE warp reduction per warp ----
    #pragma unroll
    for (int o = 16; o > 0; o >>= 1)
        vacc += __shfl_xor_sync(0xffffffffu, vacc, o);

    __shared__ float sh[WARPS_PER_BLOCK];
    if (lane == 0) sh[warp] = (float)cnt - vacc;   // sum of (1 - win) for this warp
    __syncthreads();
    if (threadIdx.x == 0) {
        float bs = 0.f;
        #pragma unroll
        for (int w = 0; w < WARPS_PER_BLOCK; w++) bs += sh[w];
        g_partials[blockIdx.x] = (double)bs;
    }
}

__global__ __launch_bounds__(256) void hloss_reduce(float* __restrict__ out, int nblocks)
{
    double s = 0.0;
    for (int i = threadIdx.x; i < nblocks; i += 256)
        s += g_partials[i];

    #pragma unroll
    for (int o = 16; o > 0; o >>= 1)
        s += __shfl_down_sync(0xffffffffu, s, o);

    __shared__ double sh[8];
    const int warp = threadIdx.x >> 5;
    const int lane = threadIdx.x & 31;
    if (lane == 0) sh[warp] = s;
    __syncthreads();
    if (threadIdx.x == 0) {
        double tot = 0.0;
        #pragma unroll
        for (int w = 0; w < 8; w++) tot += sh[w];
        out[0] = (float)tot;
    }
}

extern "C" void kernel_launch(void* const* d_in, const int* in_sizes, int n_in,
                              void* d_out, int out_size)
{
    const float* outputs = (const float*)d_in[0];   // [B, 1000] fp32
    const int*   target  = (const int*)d_in[1];     // [B] int32
    const int B = in_sizes[1];

    // 1024 blocks x 8 warps = 8192 warps; rpw = 4 for B = 32768
    int nblocks = 1024;
    int nwarps  = nblocks * WARPS_PER_BLOCK;
    int rpw     = (B + nwarps - 1) / nwarps;
    // shrink grid if B is small so every block has work
    while (nblocks > 1 && (size_t)(nblocks - 1) * WARPS_PER_BLOCK * rpw >= (size_t)B)
        nblocks--;

    hloss_main<<<nblocks, THREADS>>>(outputs, target, B, rpw);
    hloss_reduce<<<1, 256>>>((float*)d_out, nblocks);
}